// round 2
// baseline (speedup 1.0000x reference)
#include <cuda_runtime.h>
#include <math.h>
#include <stdint.h>

// ---------------- problem constants ----------------
#define NLITS 4000
#define NCLS  8000
#define E     128
#define H1    400
#define H2    200
#define TSTEPS 30
#define LIT_STRIDE 512   // max clauses per literal (mean 160, std 12.5 -> safe)
#define CLS_STRIDE 256   // max literals per clause (mean 80,  std 8.9  -> safe)
#define VOTE_BLOCKS ((NLITS + 7) / 8)

// ---------------- device scratch (static, allocation-free) ----------------
__device__ float g_Lh[NLITS * E];
__device__ float g_Lc[NLITS * E];
__device__ float g_Ch[NCLS * E];
__device__ float g_Cc[NCLS * E];
__device__ float g_buf1[NCLS * H1];    // MLP hidden 1 (max rows = NCLS)
__device__ float g_buf2[NCLS * H2];    // MLP hidden 2
__device__ float g_mlp[NCLS * E];      // MLP output (pre-aggregation)
__device__ float g_msgs[NCLS * E];     // aggregated messages
__device__ float g_gatesC[NCLS * 4 * E];
__device__ float g_gatesL[NLITS * 4 * E];
__device__ int   g_lit_idx[(size_t)NLITS * LIT_STRIDE];
__device__ int   g_lit_len[NLITS];
__device__ int   g_cls_idx[(size_t)NCLS * CLS_STRIDE];
__device__ int   g_cls_len[NCLS];
__device__ float g_partials[VOTE_BLOCKS];

// ---------------- adjacency builders (deterministic, warp-ballot compaction) ----------------
// literal lists: for literal l, clauses c with M[l][c] != 0. Coalesced row scan.
__global__ void build_lit_kernel(const float* __restrict__ M) {
    int l = blockIdx.x * (blockDim.x >> 5) + (threadIdx.x >> 5);
    int lane = threadIdx.x & 31;
    if (l >= NLITS) return;
    const float* row = M + (size_t)l * NCLS;
    int cnt = 0;
    for (int c0 = 0; c0 < NCLS; c0 += 32) {
        float v = row[c0 + lane];
        unsigned mask = __ballot_sync(0xffffffffu, v != 0.0f);
        if (v != 0.0f) {
            int pos = cnt + __popc(mask & ((1u << lane) - 1u));
            if (pos < LIT_STRIDE) g_lit_idx[(size_t)l * LIT_STRIDE + pos] = c0 + lane;
        }
        cnt += __popc(mask);
    }
    if (lane == 0) g_lit_len[l] = cnt < LIT_STRIDE ? cnt : LIT_STRIDE;
}

// clause lists: for clause c, literals l with M[l][c] != 0. Strided scan;
// 8 consecutive clauses per block keeps sector reuse in L2.
__global__ void build_cls_kernel(const float* __restrict__ M) {
    int c = blockIdx.x * (blockDim.x >> 5) + (threadIdx.x >> 5);
    int lane = threadIdx.x & 31;
    if (c >= NCLS) return;
    int cnt = 0;
    for (int l0 = 0; l0 < NLITS; l0 += 32) {
        float v = M[(size_t)(l0 + lane) * NCLS + c];
        unsigned mask = __ballot_sync(0xffffffffu, v != 0.0f);
        if (v != 0.0f) {
            int pos = cnt + __popc(mask & ((1u << lane) - 1u));
            if (pos < CLS_STRIDE) g_cls_idx[(size_t)c * CLS_STRIDE + pos] = l0 + lane;
        }
        cnt += __popc(mask);
    }
    if (lane == 0) g_cls_len[c] = cnt < CLS_STRIDE ? cnt : CLS_STRIDE;
}

// ---------------- state init ----------------
__global__ void init_state_kernel(float* __restrict__ h, float* __restrict__ c,
                                  const float* __restrict__ init_vec, int nrows) {
    int i = blockIdx.x * blockDim.x + threadIdx.x;
    if (i < nrows * E) {
        h[i] = init_vec[i & (E - 1)];
        c[i] = 0.0f;
    }
}

// ---------------- tiled fp32 GEMM:  C = act( A @ B^T [+ A2 @ B2^T] + bias ) ----------------
// A: [M,K] row-major, B: [N,K] row-major (both K-contiguous -> "NT" layout).
// 128x128 block tile, BK=8, 256 threads, 8x8 per-thread micro-tile.
template <bool RELU, bool DUAL>
__global__ void __launch_bounds__(256) gemm_nt_kernel(
    const float* __restrict__ A, const float* __restrict__ B,
    const float* __restrict__ A2, const float* __restrict__ B2,
    const float* __restrict__ bias, float* __restrict__ C,
    int M, int N, int K, int K2)
{
    __shared__ float As[8][128];
    __shared__ float Bs[8][128];

    const int tid = threadIdx.x;
    const int m0 = blockIdx.y * 128;
    const int n0 = blockIdx.x * 128;
    const int tx = tid & 15;   // 0..15 over N
    const int ty = tid >> 4;   // 0..15 over M
    const int lr = tid >> 1;          // 0..127 row within tile (for loads)
    const int lk = (tid & 1) * 4;     // 0 or 4 (k sub-chunk)

    float acc[8][8];
#pragma unroll
    for (int i = 0; i < 8; i++)
#pragma unroll
        for (int j = 0; j < 8; j++) acc[i][j] = 0.0f;

    const int npass = DUAL ? 2 : 1;
    for (int pass = 0; pass < npass; pass++) {
        const float* Ap = (DUAL && pass) ? A2 : A;
        const float* Bp = (DUAL && pass) ? B2 : B;
        const int Kp = (DUAL && pass) ? K2 : K;
        for (int k0 = 0; k0 < Kp; k0 += 8) {
            float4 av = make_float4(0.f, 0.f, 0.f, 0.f);
            float4 bv = make_float4(0.f, 0.f, 0.f, 0.f);
            if (m0 + lr < M) av = *(const float4*)(Ap + (size_t)(m0 + lr) * Kp + k0 + lk);
            if (n0 + lr < N) bv = *(const float4*)(Bp + (size_t)(n0 + lr) * Kp + k0 + lk);
            __syncthreads();
            As[lk + 0][lr] = av.x; As[lk + 1][lr] = av.y;
            As[lk + 2][lr] = av.z; As[lk + 3][lr] = av.w;
            Bs[lk + 0][lr] = bv.x; Bs[lk + 1][lr] = bv.y;
            Bs[lk + 2][lr] = bv.z; Bs[lk + 3][lr] = bv.w;
            __syncthreads();
#pragma unroll
            for (int k = 0; k < 8; k++) {
                float4 a0 = *(const float4*)&As[k][ty * 8];
                float4 a1 = *(const float4*)&As[k][ty * 8 + 4];
                float4 b0 = *(const float4*)&Bs[k][tx * 8];
                float4 b1 = *(const float4*)&Bs[k][tx * 8 + 4];
                float a[8] = {a0.x, a0.y, a0.z, a0.w, a1.x, a1.y, a1.z, a1.w};
                float b[8] = {b0.x, b0.y, b0.z, b0.w, b1.x, b1.y, b1.z, b1.w};
#pragma unroll
                for (int i = 0; i < 8; i++)
#pragma unroll
                    for (int j = 0; j < 8; j++)
                        acc[i][j] = fmaf(a[i], b[j], acc[i][j]);
            }
        }
    }

    // epilogue: + bias, optional relu, guarded store
#pragma unroll
    for (int i = 0; i < 8; i++) {
        int m = m0 + ty * 8 + i;
        if (m >= M) continue;
#pragma unroll
        for (int j = 0; j < 8; j++) {
            int n = n0 + tx * 8 + j;
            if (n >= N) continue;
            float v = acc[i][j] + bias[n];
            if (RELU) v = fmaxf(v, 0.0f);
            C[(size_t)m * N + n] = v;
        }
    }
}

// ---------------- SpMM gather:  out[r,:] = sum_{j in list(r)} in[idx[j],:]  (E=128) ----------------
__global__ void spmm_gather_kernel(const int* __restrict__ idx, const int* __restrict__ len,
                                   int stride, const float* __restrict__ in,
                                   float* __restrict__ out, int nrows) {
    int r = (blockIdx.x * blockDim.x + threadIdx.x) >> 5;
    if (r >= nrows) return;
    int lane = threadIdx.x & 31;
    const int* lst = idx + (size_t)r * stride;
    int n = len[r];
    float4 acc = make_float4(0.f, 0.f, 0.f, 0.f);
    int j = 0;
    for (; j + 4 <= n; j += 4) {
        int i0 = lst[j], i1 = lst[j + 1], i2 = lst[j + 2], i3 = lst[j + 3];
        float4 v0 = ((const float4*)(in + (size_t)i0 * E))[lane];
        float4 v1 = ((const float4*)(in + (size_t)i1 * E))[lane];
        float4 v2 = ((const float4*)(in + (size_t)i2 * E))[lane];
        float4 v3 = ((const float4*)(in + (size_t)i3 * E))[lane];
        acc.x += v0.x + v1.x + v2.x + v3.x;
        acc.y += v0.y + v1.y + v2.y + v3.y;
        acc.z += v0.z + v1.z + v2.z + v3.z;
        acc.w += v0.w + v1.w + v2.w + v3.w;
    }
    for (; j < n; j++) {
        float4 v = ((const float4*)(in + (size_t)lst[j] * E))[lane];
        acc.x += v.x; acc.y += v.y; acc.z += v.z; acc.w += v.w;
    }
    ((float4*)(out + (size_t)r * E))[lane] = acc;
}

// ---------------- LSTM pointwise ----------------
__device__ __forceinline__ float sigmoidf_(float x) { return 1.0f / (1.0f + expf(-x)); }

__global__ void lstm_pointwise_kernel(const float* __restrict__ gates,
                                      float* __restrict__ h, float* __restrict__ c,
                                      int nrows) {
    int i = blockIdx.x * blockDim.x + threadIdx.x;
    if (i >= nrows * E) return;
    int row = i >> 7;
    int col = i & (E - 1);
    const float* g = gates + (size_t)row * (4 * E);
    float ig = sigmoidf_(g[col]);
    float fg = sigmoidf_(g[E + col]);
    float gg = tanhf(g[2 * E + col]);
    float og = sigmoidf_(g[3 * E + col]);
    float c2 = fg * c[i] + ig * gg;
    c[i] = c2;
    h[i] = og * tanhf(c2);
}

// ---------------- vote + reduction ----------------
__global__ void vote_partial_kernel(const float* __restrict__ X2,
                                    const float* __restrict__ W3,
                                    const float* __restrict__ b3,
                                    float* __restrict__ partials) {
    int warp = (blockIdx.x * blockDim.x + threadIdx.x) >> 5;
    int lane = threadIdx.x & 31;
    float vote = 0.0f;
    if (warp < NLITS) {
        const float* x = X2 + (size_t)warp * H2;
        float s = 0.0f;
        for (int jj = lane; jj < H2; jj += 32) s += x[jj] * W3[jj];
#pragma unroll
        for (int o = 16; o; o >>= 1) s += __shfl_down_sync(0xffffffffu, s, o);
        if (lane == 0) vote = sigmoidf_(s + b3[0]);
    }
    __shared__ float sm[8];
    if (lane == 0) sm[threadIdx.x >> 5] = vote;
    __syncthreads();
    if (threadIdx.x == 0) {
        float t = 0.0f;
        for (int w = 0; w < 8; w++) t += sm[w];
        partials[blockIdx.x] = t;
    }
}

__global__ void finalize_kernel(const float* __restrict__ partials, int n,
                                float* __restrict__ out) {
    __shared__ float sm[512];
    float s = 0.0f;
    for (int i = threadIdx.x; i < n; i += blockDim.x) s += partials[i];
    sm[threadIdx.x] = s;
    __syncthreads();
    for (int o = 256; o; o >>= 1) {
        if (threadIdx.x < o) sm[threadIdx.x] += sm[threadIdx.x + o];
        __syncthreads();
    }
    if (threadIdx.x == 0) {
        float avg = sm[0] / (float)NLITS;
        out[0] = logf(avg / (1.0f - avg));
    }
}

// ---------------- host-side launch helpers ----------------
template <bool RELU, bool DUAL>
static inline void launch_gemm(const float* A, const float* B,
                               const float* A2, const float* B2,
                               const float* bias, float* C,
                               int M, int N, int K, int K2) {
    dim3 grid((N + 127) / 128, (M + 127) / 128);
    gemm_nt_kernel<RELU, DUAL><<<grid, 256>>>(A, B, A2, B2, bias, C, M, N, K, K2);
}

static inline float* dev_ptr(float* sym_addr) { return sym_addr; }

extern "C" void kernel_launch(void* const* d_in, const int* in_sizes, int n_in,
                              void* d_out, int out_size) {
    const float* M      = (const float*)d_in[0];
    const float* L_init = (const float*)d_in[1];
    const float* C_init = (const float*)d_in[2];
    const float* LC_W1 = (const float*)d_in[3];  const float* LC_b1 = (const float*)d_in[4];
    const float* LC_W2 = (const float*)d_in[5];  const float* LC_b2 = (const float*)d_in[6];
    const float* LC_W3 = (const float*)d_in[7];  const float* LC_b3 = (const float*)d_in[8];
    const float* CL_W1 = (const float*)d_in[9];  const float* CL_b1 = (const float*)d_in[10];
    const float* CL_W2 = (const float*)d_in[11]; const float* CL_b2 = (const float*)d_in[12];
    const float* CL_W3 = (const float*)d_in[13]; const float* CL_b3 = (const float*)d_in[14];
    const float* L_Wih = (const float*)d_in[15]; const float* L_Whh = (const float*)d_in[16];
    const float* L_b   = (const float*)d_in[17];
    const float* C_Wih = (const float*)d_in[18]; const float* C_Whh = (const float*)d_in[19];
    const float* C_b   = (const float*)d_in[20];
    const float* V_W1 = (const float*)d_in[21];  const float* V_b1 = (const float*)d_in[22];
    const float* V_W2 = (const float*)d_in[23];  const float* V_b2 = (const float*)d_in[24];
    const float* V_W3 = (const float*)d_in[25];  const float* V_b3 = (const float*)d_in[26];
    float* out = (float*)d_out;

    // resolve device-global addresses (device symbols are directly usable in <<<>>> args
    // when taken via the device-side symbol name from host in same TU with CUDA >= 11)
    float *Lh, *Lc, *Ch, *Cc, *buf1, *buf2, *mlp, *msgs, *gatesC, *gatesL, *partials;
    int *lit_idx, *lit_len, *cls_idx, *cls_len;
    cudaGetSymbolAddress((void**)&Lh, g_Lh);
    cudaGetSymbolAddress((void**)&Lc, g_Lc);
    cudaGetSymbolAddress((void**)&Ch, g_Ch);
    cudaGetSymbolAddress((void**)&Cc, g_Cc);
    cudaGetSymbolAddress((void**)&buf1, g_buf1);
    cudaGetSymbolAddress((void**)&buf2, g_buf2);
    cudaGetSymbolAddress((void**)&mlp, g_mlp);
    cudaGetSymbolAddress((void**)&msgs, g_msgs);
    cudaGetSymbolAddress((void**)&gatesC, g_gatesC);
    cudaGetSymbolAddress((void**)&gatesL, g_gatesL);
    cudaGetSymbolAddress((void**)&partials, g_partials);
    cudaGetSymbolAddress((void**)&lit_idx, g_lit_idx);
    cudaGetSymbolAddress((void**)&lit_len, g_lit_len);
    cudaGetSymbolAddress((void**)&cls_idx, g_cls_idx);
    cudaGetSymbolAddress((void**)&cls_len, g_cls_len);

    // adjacency (rebuilt each launch; deterministic)
    build_lit_kernel<<<(NLITS + 7) / 8, 256>>>(M);
    build_cls_kernel<<<(NCLS + 7) / 8, 256>>>(M);

    // state init
    init_state_kernel<<<(NLITS * E + 255) / 256, 256>>>(Lh, Lc, L_init, NLITS);
    init_state_kernel<<<(NCLS * E + 255) / 256, 256>>>(Ch, Cc, C_init, NCLS);

    for (int t = 0; t < TSTEPS; t++) {
        // literal -> clause messages: MLP(Lh), aggregate over clause neighbor lists
        launch_gemm<true,  false>(Lh,   LC_W1, nullptr, nullptr, LC_b1, buf1, NLITS, H1, E,  0);
        launch_gemm<true,  false>(buf1, LC_W2, nullptr, nullptr, LC_b2, buf2, NLITS, H2, H1, 0);
        launch_gemm<false, false>(buf2, LC_W3, nullptr, nullptr, LC_b3, mlp,  NLITS, E,  H2, 0);
        spmm_gather_kernel<<<(NCLS + 7) / 8, 256>>>(cls_idx, cls_len, CLS_STRIDE, mlp, msgs, NCLS);
        // clause LSTM gates (uses OLD Ch)
        launch_gemm<false, true>(msgs, C_Wih, Ch, C_Whh, C_b, gatesC, NCLS, 4 * E, E, E);

        // clause -> literal messages: MLP(OLD Ch), aggregate over literal neighbor lists
        launch_gemm<true,  false>(Ch,   CL_W1, nullptr, nullptr, CL_b1, buf1, NCLS, H1, E,  0);
        launch_gemm<true,  false>(buf1, CL_W2, nullptr, nullptr, CL_b2, buf2, NCLS, H2, H1, 0);
        launch_gemm<false, false>(buf2, CL_W3, nullptr, nullptr, CL_b3, mlp,  NCLS, E,  H2, 0);
        spmm_gather_kernel<<<(NLITS + 7) / 8, 256>>>(lit_idx, lit_len, LIT_STRIDE, mlp, msgs, NLITS);
        // literal LSTM gates (uses OLD Lh)
        launch_gemm<false, true>(msgs, L_Wih, Lh, L_Whh, L_b, gatesL, NLITS, 4 * E, E, E);

        // pointwise state updates (now safe to overwrite h/c in place)
        lstm_pointwise_kernel<<<(NCLS * E + 255) / 256, 256>>>(gatesC, Ch, Cc, NCLS);
        lstm_pointwise_kernel<<<(NLITS * E + 255) / 256, 256>>>(gatesL, Lh, Lc, NLITS);
    }

    // final vote MLP + mean + logit
    launch_gemm<true, false>(Lh,   V_W1, nullptr, nullptr, V_b1, buf1, NLITS, H1, E,  0);
    launch_gemm<true, false>(buf1, V_W2, nullptr, nullptr, V_b2, buf2, NLITS, H2, H1, 0);
    vote_partial_kernel<<<VOTE_BLOCKS, 256>>>(buf2, V_W3, V_b3, partials);
    finalize_kernel<<<1, 512>>>(partials, VOTE_BLOCKS, out);
}

// round 3
// speedup vs baseline: 1.0622x; 1.0622x over previous
#include <cuda_runtime.h>
#include <math.h>
#include <stdint.h>

// ---------------- problem constants ----------------
#define NLITS 4000
#define NCLS  8000
#define E     128
#define H1    400
#define H2    200
#define TSTEPS 30
#define LIT_STRIDE 512   // max clauses per literal (mean 160, std 12.5 -> safe)
#define CLS_STRIDE 256   // max literals per clause (mean 80,  std 8.9  -> safe)
#define VOTE_BLOCKS ((NLITS + 7) / 8)

// ---------------- device scratch (static, allocation-free) ----------------
__device__ float g_Lh[NLITS * E];
__device__ float g_Lc[NLITS * E];
__device__ float g_Ch[NCLS * E];
__device__ float g_Cc[NCLS * E];
__device__ float g_b1L[NLITS * H1];
__device__ float g_b1C[NCLS * H1];
__device__ float g_b2L[NLITS * H2];
__device__ float g_b2C[NCLS * H2];
__device__ float g_mlpL[NLITS * E];
__device__ float g_mlpC[NCLS * E];
__device__ float g_msgL[NLITS * E];
__device__ float g_msgC[NCLS * E];
__device__ float g_gatesC[NCLS * 4 * E];
__device__ float g_gatesL[NLITS * 4 * E];
__device__ int   g_lit_idx[(size_t)NLITS * LIT_STRIDE];
__device__ int   g_lit_len[NLITS];
__device__ int   g_cls_idx[(size_t)NCLS * CLS_STRIDE];
__device__ int   g_cls_len[NCLS];
__device__ float g_partials[VOTE_BLOCKS];

// ---------------- adjacency builders (deterministic, warp-ballot compaction) ----------------
__global__ void build_lit_kernel(const float* __restrict__ M) {
    int l = blockIdx.x * (blockDim.x >> 5) + (threadIdx.x >> 5);
    int lane = threadIdx.x & 31;
    if (l >= NLITS) return;
    const float* row = M + (size_t)l * NCLS;
    int cnt = 0;
    for (int c0 = 0; c0 < NCLS; c0 += 32) {
        float v = row[c0 + lane];
        unsigned mask = __ballot_sync(0xffffffffu, v != 0.0f);
        if (v != 0.0f) {
            int pos = cnt + __popc(mask & ((1u << lane) - 1u));
            if (pos < LIT_STRIDE) g_lit_idx[(size_t)l * LIT_STRIDE + pos] = c0 + lane;
        }
        cnt += __popc(mask);
    }
    if (lane == 0) g_lit_len[l] = cnt < LIT_STRIDE ? cnt : LIT_STRIDE;
}

__global__ void build_cls_kernel(const float* __restrict__ M) {
    int c = blockIdx.x * (blockDim.x >> 5) + (threadIdx.x >> 5);
    int lane = threadIdx.x & 31;
    if (c >= NCLS) return;
    int cnt = 0;
    for (int l0 = 0; l0 < NLITS; l0 += 32) {
        float v = M[(size_t)(l0 + lane) * NCLS + c];
        unsigned mask = __ballot_sync(0xffffffffu, v != 0.0f);
        if (v != 0.0f) {
            int pos = cnt + __popc(mask & ((1u << lane) - 1u));
            if (pos < CLS_STRIDE) g_cls_idx[(size_t)c * CLS_STRIDE + pos] = l0 + lane;
        }
        cnt += __popc(mask);
    }
    if (lane == 0) g_cls_len[c] = cnt < CLS_STRIDE ? cnt : CLS_STRIDE;
}

// ---------------- state init ----------------
__global__ void init_state_kernel(float* __restrict__ h, float* __restrict__ c,
                                  const float* __restrict__ init_vec, int nrows) {
    int i = blockIdx.x * blockDim.x + threadIdx.x;
    if (i < nrows * E) {
        h[i] = init_vec[i & (E - 1)];
        c[i] = 0.0f;
    }
}

// ---------------- segmented, double-buffered fp32 GEMM ----------------
// C = act( A @ B^T [+ A2 @ B2^T] + bias ). A:[M,K] row-major, B:[N,K] row-major.
// blockIdx.z selects segment (independent problem with same N,K shapes).
struct Seg {
    const float* A;  const float* B;
    const float* A2; const float* B2;
    const float* bias; float* C;
    int M;
};

template <int TM, int TN, bool RELU, bool DUAL>
__global__ void __launch_bounds__((TM / 8) * (TN / 8)) gemm_seg_kernel(
    Seg s0, Seg s1, int N, int K, int K2)
{
    const Seg s = (blockIdx.z == 0) ? s0 : s1;
    const int m0 = blockIdx.y * TM;
    if (m0 >= s.M) return;
    const int n0 = blockIdx.x * TN;

    constexpr int THREADS = (TM / 8) * (TN / 8);
    constexpr int NA4 = (TM * 2) / THREADS;   // float4 loads per thread for A tile
    static_assert(TN * 2 == THREADS, "B-tile load mapping expects TN*2 == THREADS");
    static_assert(NA4 >= 1, "bad tile config");

    __shared__ float As[2][8][TM];
    __shared__ float Bs[2][8][TN];

    const int tid = threadIdx.x;
    const int tx = tid % (TN / 8);
    const int ty = tid / (TN / 8);
    const int brow = tid >> 1;
    const int blk = (tid & 1) * 4;

    float acc[8][8];
#pragma unroll
    for (int i = 0; i < 8; i++)
#pragma unroll
        for (int j = 0; j < 8; j++) acc[i][j] = 0.0f;

    float4 aReg[NA4];
    float4 bReg;

    const int npass = DUAL ? 2 : 1;
    for (int pass = 0; pass < npass; pass++) {
        const float* Ap = (DUAL && pass) ? s.A2 : s.A;
        const float* Bp = (DUAL && pass) ? s.B2 : s.B;
        const int Kp = (DUAL && pass) ? K2 : K;
        const int ntiles = Kp >> 3;

        // --- prologue: load k-tile 0 ---
        {
            const int k0 = 0;
#pragma unroll
            for (int i = 0; i < NA4; i++) {
                int idx = tid + i * THREADS;
                int ar = idx >> 1, alk = (idx & 1) * 4;
                int grow = m0 + ar;
                aReg[i] = (grow < s.M)
                    ? *(const float4*)(Ap + (size_t)grow * Kp + k0 + alk)
                    : make_float4(0.f, 0.f, 0.f, 0.f);
            }
            int gcol = n0 + brow;
            bReg = (gcol < N)
                ? *(const float4*)(Bp + (size_t)gcol * Kp + k0 + blk)
                : make_float4(0.f, 0.f, 0.f, 0.f);
        }
        if (pass) __syncthreads();  // previous pass may still be reading smem
        {
#pragma unroll
            for (int i = 0; i < NA4; i++) {
                int idx = tid + i * THREADS;
                int ar = idx >> 1, alk = (idx & 1) * 4;
                As[0][alk + 0][ar] = aReg[i].x; As[0][alk + 1][ar] = aReg[i].y;
                As[0][alk + 2][ar] = aReg[i].z; As[0][alk + 3][ar] = aReg[i].w;
            }
            Bs[0][blk + 0][brow] = bReg.x; Bs[0][blk + 1][brow] = bReg.y;
            Bs[0][blk + 2][brow] = bReg.z; Bs[0][blk + 3][brow] = bReg.w;
        }
        __syncthreads();

        int buf = 0;
        for (int kt = 0; kt < ntiles; kt++) {
            if (kt + 1 < ntiles) {
                const int k0 = (kt + 1) << 3;
#pragma unroll
                for (int i = 0; i < NA4; i++) {
                    int idx = tid + i * THREADS;
                    int ar = idx >> 1, alk = (idx & 1) * 4;
                    int grow = m0 + ar;
                    aReg[i] = (grow < s.M)
                        ? *(const float4*)(Ap + (size_t)grow * Kp + k0 + alk)
                        : make_float4(0.f, 0.f, 0.f, 0.f);
                }
                int gcol = n0 + brow;
                bReg = (gcol < N)
                    ? *(const float4*)(Bp + (size_t)gcol * Kp + k0 + blk)
                    : make_float4(0.f, 0.f, 0.f, 0.f);
            }
#pragma unroll
            for (int k = 0; k < 8; k++) {
                float a[8], b[8];
                *(float4*)&a[0] = *(const float4*)&As[buf][k][ty * 8];
                *(float4*)&a[4] = *(const float4*)&As[buf][k][ty * 8 + 4];
                *(float4*)&b[0] = *(const float4*)&Bs[buf][k][tx * 8];
                *(float4*)&b[4] = *(const float4*)&Bs[buf][k][tx * 8 + 4];
#pragma unroll
                for (int i = 0; i < 8; i++)
#pragma unroll
                    for (int j = 0; j < 8; j++)
                        acc[i][j] = fmaf(a[i], b[j], acc[i][j]);
            }
            if (kt + 1 < ntiles) {
                const int nb = buf ^ 1;
#pragma unroll
                for (int i = 0; i < NA4; i++) {
                    int idx = tid + i * THREADS;
                    int ar = idx >> 1, alk = (idx & 1) * 4;
                    As[nb][alk + 0][ar] = aReg[i].x; As[nb][alk + 1][ar] = aReg[i].y;
                    As[nb][alk + 2][ar] = aReg[i].z; As[nb][alk + 3][ar] = aReg[i].w;
                }
                Bs[nb][blk + 0][brow] = bReg.x; Bs[nb][blk + 1][brow] = bReg.y;
                Bs[nb][blk + 2][brow] = bReg.z; Bs[nb][blk + 3][brow] = bReg.w;
                __syncthreads();
                buf = nb;
            }
        }
    }

    // epilogue: + bias, optional relu, guarded store
#pragma unroll
    for (int i = 0; i < 8; i++) {
        int m = m0 + ty * 8 + i;
        if (m >= s.M) continue;
#pragma unroll
        for (int j = 0; j < 8; j++) {
            int n = n0 + tx * 8 + j;
            if (n >= N) continue;
            float v = acc[i][j] + s.bias[n];
            if (RELU) v = fmaxf(v, 0.0f);
            s.C[(size_t)m * N + n] = v;
        }
    }
}

template <int TM, int TN, bool RELU, bool DUAL>
static inline void launch_seg(Seg s0, Seg s1, int nz, int N, int K, int K2) {
    int mmax = s0.M;
    if (nz > 1 && s1.M > mmax) mmax = s1.M;
    dim3 grid((N + TN - 1) / TN, (mmax + TM - 1) / TM, nz);
    gemm_seg_kernel<TM, TN, RELU, DUAL><<<grid, (TM / 8) * (TN / 8)>>>(s0, s1, N, K, K2);
}

// ---------------- SpMM gather:  out[r,:] = sum_{j in list(r)} in[idx[j],:]  (E=128) ----------------
__global__ void spmm_gather_kernel(const int* __restrict__ idx, const int* __restrict__ len,
                                   int stride, const float* __restrict__ in,
                                   float* __restrict__ out, int nrows) {
    int r = (blockIdx.x * blockDim.x + threadIdx.x) >> 5;
    if (r >= nrows) return;
    int lane = threadIdx.x & 31;
    const int* lst = idx + (size_t)r * stride;
    int n = len[r];
    float4 acc = make_float4(0.f, 0.f, 0.f, 0.f);
    int j = 0;
    for (; j + 4 <= n; j += 4) {
        int i0 = lst[j], i1 = lst[j + 1], i2 = lst[j + 2], i3 = lst[j + 3];
        float4 v0 = ((const float4*)(in + (size_t)i0 * E))[lane];
        float4 v1 = ((const float4*)(in + (size_t)i1 * E))[lane];
        float4 v2 = ((const float4*)(in + (size_t)i2 * E))[lane];
        float4 v3 = ((const float4*)(in + (size_t)i3 * E))[lane];
        acc.x += v0.x + v1.x + v2.x + v3.x;
        acc.y += v0.y + v1.y + v2.y + v3.y;
        acc.z += v0.z + v1.z + v2.z + v3.z;
        acc.w += v0.w + v1.w + v2.w + v3.w;
    }
    for (; j < n; j++) {
        float4 v = ((const float4*)(in + (size_t)lst[j] * E))[lane];
        acc.x += v.x; acc.y += v.y; acc.z += v.z; acc.w += v.w;
    }
    ((float4*)(out + (size_t)r * E))[lane] = acc;
}

// ---------------- LSTM pointwise (both node types in one launch) ----------------
__device__ __forceinline__ float sigmoidf_(float x) { return 1.0f / (1.0f + expf(-x)); }

__global__ void lstm_pointwise_both(const float* __restrict__ gC,
                                    float* __restrict__ Ch, float* __restrict__ Cc,
                                    const float* __restrict__ gL,
                                    float* __restrict__ Lh, float* __restrict__ Lc) {
    int i = blockIdx.x * blockDim.x + threadIdx.x;
    const int totalC = NCLS * E;
    if (i >= totalC + NLITS * E) return;

    const float* g; float* h; float* c; int e;
    if (i < totalC) { g = gC; h = Ch; c = Cc; e = i; }
    else            { g = gL; h = Lh; c = Lc; e = i - totalC; }

    int row = e >> 7;
    int col = e & (E - 1);
    const float* gr = g + (size_t)row * (4 * E);
    float ig = sigmoidf_(gr[col]);
    float fg = sigmoidf_(gr[E + col]);
    float gg = tanhf(gr[2 * E + col]);
    float og = sigmoidf_(gr[3 * E + col]);
    float c2 = fg * c[e] + ig * gg;
    c[e] = c2;
    h[e] = og * tanhf(c2);
}

// ---------------- vote + reduction ----------------
__global__ void vote_partial_kernel(const float* __restrict__ X2,
                                    const float* __restrict__ W3,
                                    const float* __restrict__ b3,
                                    float* __restrict__ partials) {
    int warp = (blockIdx.x * blockDim.x + threadIdx.x) >> 5;
    int lane = threadIdx.x & 31;
    float vote = 0.0f;
    if (warp < NLITS) {
        const float* x = X2 + (size_t)warp * H2;
        float s = 0.0f;
        for (int jj = lane; jj < H2; jj += 32) s += x[jj] * W3[jj];
#pragma unroll
        for (int o = 16; o; o >>= 1) s += __shfl_down_sync(0xffffffffu, s, o);
        if (lane == 0) vote = sigmoidf_(s + b3[0]);
    }
    __shared__ float sm[8];
    if (lane == 0) sm[threadIdx.x >> 5] = vote;
    __syncthreads();
    if (threadIdx.x == 0) {
        float t = 0.0f;
        for (int w = 0; w < 8; w++) t += sm[w];
        partials[blockIdx.x] = t;
    }
}

__global__ void finalize_kernel(const float* __restrict__ partials, int n,
                                float* __restrict__ out) {
    __shared__ float sm[512];
    float s = 0.0f;
    for (int i = threadIdx.x; i < n; i += blockDim.x) s += partials[i];
    sm[threadIdx.x] = s;
    __syncthreads();
    for (int o = 256; o; o >>= 1) {
        if (threadIdx.x < o) sm[threadIdx.x] += sm[threadIdx.x + o];
        __syncthreads();
    }
    if (threadIdx.x == 0) {
        float avg = sm[0] / (float)NLITS;
        out[0] = logf(avg / (1.0f - avg));
    }
}

extern "C" void kernel_launch(void* const* d_in, const int* in_sizes, int n_in,
                              void* d_out, int out_size) {
    const float* M      = (const float*)d_in[0];
    const float* L_init = (const float*)d_in[1];
    const float* C_init = (const float*)d_in[2];
    const float* LC_W1 = (const float*)d_in[3];  const float* LC_b1 = (const float*)d_in[4];
    const float* LC_W2 = (const float*)d_in[5];  const float* LC_b2 = (const float*)d_in[6];
    const float* LC_W3 = (const float*)d_in[7];  const float* LC_b3 = (const float*)d_in[8];
    const float* CL_W1 = (const float*)d_in[9];  const float* CL_b1 = (const float*)d_in[10];
    const float* CL_W2 = (const float*)d_in[11]; const float* CL_b2 = (const float*)d_in[12];
    const float* CL_W3 = (const float*)d_in[13]; const float* CL_b3 = (const float*)d_in[14];
    const float* L_Wih = (const float*)d_in[15]; const float* L_Whh = (const float*)d_in[16];
    const float* L_b   = (const float*)d_in[17];
    const float* C_Wih = (const float*)d_in[18]; const float* C_Whh = (const float*)d_in[19];
    const float* C_b   = (const float*)d_in[20];
    const float* V_W1 = (const float*)d_in[21];  const float* V_b1 = (const float*)d_in[22];
    const float* V_W2 = (const float*)d_in[23];  const float* V_b2 = (const float*)d_in[24];
    const float* V_W3 = (const float*)d_in[25];  const float* V_b3 = (const float*)d_in[26];
    float* out = (float*)d_out;

    float *Lh, *Lc, *Ch, *Cc, *b1L, *b1C, *b2L, *b2C, *mlpL, *mlpC, *msgL, *msgC;
    float *gatesC, *gatesL, *partials;
    int *lit_idx, *lit_len, *cls_idx, *cls_len;
    cudaGetSymbolAddress((void**)&Lh, g_Lh);
    cudaGetSymbolAddress((void**)&Lc, g_Lc);
    cudaGetSymbolAddress((void**)&Ch, g_Ch);
    cudaGetSymbolAddress((void**)&Cc, g_Cc);
    cudaGetSymbolAddress((void**)&b1L, g_b1L);
    cudaGetSymbolAddress((void**)&b1C, g_b1C);
    cudaGetSymbolAddress((void**)&b2L, g_b2L);
    cudaGetSymbolAddress((void**)&b2C, g_b2C);
    cudaGetSymbolAddress((void**)&mlpL, g_mlpL);
    cudaGetSymbolAddress((void**)&mlpC, g_mlpC);
    cudaGetSymbolAddress((void**)&msgL, g_msgL);
    cudaGetSymbolAddress((void**)&msgC, g_msgC);
    cudaGetSymbolAddress((void**)&gatesC, g_gatesC);
    cudaGetSymbolAddress((void**)&gatesL, g_gatesL);
    cudaGetSymbolAddress((void**)&partials, g_partials);
    cudaGetSymbolAddress((void**)&lit_idx, g_lit_idx);
    cudaGetSymbolAddress((void**)&lit_len, g_lit_len);
    cudaGetSymbolAddress((void**)&cls_idx, g_cls_idx);
    cudaGetSymbolAddress((void**)&cls_len, g_cls_len);

    // adjacency (rebuilt each launch; deterministic)
    build_lit_kernel<<<(NLITS + 7) / 8, 256>>>(M);
    build_cls_kernel<<<(NCLS + 7) / 8, 256>>>(M);

    // state init
    init_state_kernel<<<(NLITS * E + 255) / 256, 256>>>(Lh, Lc, L_init, NLITS);
    init_state_kernel<<<(NCLS * E + 255) / 256, 256>>>(Ch, Cc, C_init, NCLS);

    Seg dummy = {};

    for (int t = 0; t < TSTEPS; t++) {
        // --- both MLP chains, segment-combined (literals: LC weights, clauses: CL weights) ---
        Seg m1a = {Lh,  LC_W1, nullptr, nullptr, LC_b1, b1L, NLITS};
        Seg m1b = {Ch,  CL_W1, nullptr, nullptr, CL_b1, b1C, NCLS};
        launch_seg<128, 64, true, false>(m1a, m1b, 2, H1, E, 0);

        Seg m2a = {b1L, LC_W2, nullptr, nullptr, LC_b2, b2L, NLITS};
        Seg m2b = {b1C, CL_W2, nullptr, nullptr, CL_b2, b2C, NCLS};
        launch_seg<128, 64, true, false>(m2a, m2b, 2, H2, H1, 0);

        Seg m3a = {b2L, LC_W3, nullptr, nullptr, LC_b3, mlpL, NLITS};
        Seg m3b = {b2C, CL_W3, nullptr, nullptr, CL_b3, mlpC, NCLS};
        launch_seg<128, 64, false, false>(m3a, m3b, 2, E, H2, 0);

        // --- message aggregation (sparse gathers) ---
        spmm_gather_kernel<<<(NCLS + 7) / 8, 256>>>(cls_idx, cls_len, CLS_STRIDE, mlpL, msgC, NCLS);
        spmm_gather_kernel<<<(NLITS + 7) / 8, 256>>>(lit_idx, lit_len, LIT_STRIDE, mlpC, msgL, NLITS);

        // --- LSTM gate GEMMs, segment-combined (use PRE-update h states) ---
        Seg ga = {msgC, C_Wih, Ch, C_Whh, C_b, gatesC, NCLS};
        Seg gb = {msgL, L_Wih, Lh, L_Whh, L_b, gatesL, NLITS};
        launch_seg<128, 128, false, true>(ga, gb, 2, 4 * E, E, E);

        // --- pointwise state updates (safe to overwrite h/c now) ---
        lstm_pointwise_both<<<((NCLS + NLITS) * E + 255) / 256, 256>>>(
            gatesC, Ch, Cc, gatesL, Lh, Lc);
    }

    // final vote MLP + mean + logit (literal segment only)
    Seg v1 = {Lh,  V_W1, nullptr, nullptr, V_b1, b1L, NLITS};
    launch_seg<128, 64, true, false>(v1, dummy, 1, H1, E, 0);
    Seg v2 = {b1L, V_W2, nullptr, nullptr, V_b2, b2L, NLITS};
    launch_seg<128, 64, true, false>(v2, dummy, 1, H2, H1, 0);
    vote_partial_kernel<<<VOTE_BLOCKS, 256>>>(b2L, V_W3, V_b3, partials);
    finalize_kernel<<<1, 512>>>(partials, VOTE_BLOCKS, out);
}

// round 4
// speedup vs baseline: 1.7250x; 1.6240x over previous
#include <cuda_runtime.h>
#include <cuda_bf16.h>
#include <math.h>
#include <stdint.h>

// ---------------- problem constants ----------------
#define NLITS 4000
#define NCLS  8000
#define E     128
#define H1    400
#define H2    200
#define NG    512          // 4*E LSTM gates
#define TSTEPS 30
#define LIT_STRIDE 512
#define CLS_STRIDE 256
#define VOTE_BLOCKS ((NLITS + 7) / 8)

// padded K dims (multiples of 32 for BK)
#define K1P 128            // E
#define K2P 416            // H1 padded
#define K3P 224            // H2 padded

typedef __nv_bfloat16 bf16;
typedef __nv_bfloat162 bf162;

// ---------------- device scratch (static, allocation-free; BSS zero-init) ----------------
__device__ bf16 g_LhH[NLITS * E], g_LhL[NLITS * E];
__device__ bf16 g_ChH[NCLS * E],  g_ChL[NCLS * E];
__device__ float g_Lc[NLITS * E], g_Cc[NCLS * E];

__device__ bf16 g_b1LH[NLITS * K2P], g_b1LL[NLITS * K2P];
__device__ bf16 g_b1CH[NCLS * K2P],  g_b1CL[NCLS * K2P];
__device__ bf16 g_b2LH[NLITS * K3P], g_b2LL[NLITS * K3P];
__device__ bf16 g_b2CH[NCLS * K3P],  g_b2CL[NCLS * K3P];
__device__ bf16 g_mlpLH[NLITS * E],  g_mlpLL[NLITS * E];
__device__ bf16 g_mlpCH[NCLS * E],   g_mlpCL[NCLS * E];
__device__ bf16 g_msgLH[NLITS * E],  g_msgLL[NLITS * E];
__device__ bf16 g_msgCH[NCLS * E],   g_msgCL[NCLS * E];
__device__ float g_gatesC[NCLS * NG], g_gatesL[NLITS * NG];

// split weights (padded)
__device__ bf16 g_LC1H[H1 * K1P], g_LC1L[H1 * K1P];
__device__ bf16 g_LC2H[H2 * K2P], g_LC2L[H2 * K2P];
__device__ bf16 g_LC3H[E  * K3P], g_LC3L[E  * K3P];
__device__ bf16 g_CL1H[H1 * K1P], g_CL1L[H1 * K1P];
__device__ bf16 g_CL2H[H2 * K2P], g_CL2L[H2 * K2P];
__device__ bf16 g_CL3H[E  * K3P], g_CL3L[E  * K3P];
__device__ bf16 g_CWiH[NG * K1P], g_CWiL[NG * K1P];
__device__ bf16 g_CWhH[NG * K1P], g_CWhL[NG * K1P];
__device__ bf16 g_LWiH[NG * K1P], g_LWiL[NG * K1P];
__device__ bf16 g_LWhH[NG * K1P], g_LWhL[NG * K1P];
__device__ bf16 g_VW1H[H1 * K1P], g_VW1L[H1 * K1P];
__device__ bf16 g_VW2H[H2 * K2P], g_VW2L[H2 * K2P];

__device__ int g_lit_idx[(size_t)NLITS * LIT_STRIDE];
__device__ int g_lit_len[NLITS];
__device__ int g_cls_idx[(size_t)NCLS * CLS_STRIDE];
__device__ int g_cls_len[NCLS];
__device__ float g_partials[VOTE_BLOCKS];

__device__ __forceinline__ void split_val(float v, bf16& hi, bf16& lo) {
    hi = __float2bfloat16_rn(v);
    lo = __float2bfloat16_rn(v - __bfloat162float(hi));
}

// ---------------- adjacency builders ----------------
__global__ void build_lit_kernel(const float* __restrict__ M) {
    int l = blockIdx.x * (blockDim.x >> 5) + (threadIdx.x >> 5);
    int lane = threadIdx.x & 31;
    if (l >= NLITS) return;
    const float* row = M + (size_t)l * NCLS;
    int cnt = 0;
    for (int c0 = 0; c0 < NCLS; c0 += 32) {
        float v = row[c0 + lane];
        unsigned mask = __ballot_sync(0xffffffffu, v != 0.0f);
        if (v != 0.0f) {
            int pos = cnt + __popc(mask & ((1u << lane) - 1u));
            if (pos < LIT_STRIDE) g_lit_idx[(size_t)l * LIT_STRIDE + pos] = c0 + lane;
        }
        cnt += __popc(mask);
    }
    if (lane == 0) g_lit_len[l] = cnt < LIT_STRIDE ? cnt : LIT_STRIDE;
}

__global__ void build_cls_kernel(const float* __restrict__ M) {
    int c = blockIdx.x * (blockDim.x >> 5) + (threadIdx.x >> 5);
    int lane = threadIdx.x & 31;
    if (c >= NCLS) return;
    int cnt = 0;
    for (int l0 = 0; l0 < NLITS; l0 += 32) {
        float v = M[(size_t)(l0 + lane) * NCLS + c];
        unsigned mask = __ballot_sync(0xffffffffu, v != 0.0f);
        if (v != 0.0f) {
            int pos = cnt + __popc(mask & ((1u << lane) - 1u));
            if (pos < CLS_STRIDE) g_cls_idx[(size_t)c * CLS_STRIDE + pos] = l0 + lane;
        }
        cnt += __popc(mask);
    }
    if (lane == 0) g_cls_len[c] = cnt < CLS_STRIDE ? cnt : CLS_STRIDE;
}

// ---------------- weight splitter (with K padding) ----------------
__global__ void split_weight_kernel(const float* __restrict__ in, bf16* __restrict__ hi,
                                    bf16* __restrict__ lo, int rows, int K, int Kpad) {
    int i = blockIdx.x * blockDim.x + threadIdx.x;
    if (i >= rows * Kpad) return;
    int r = i / Kpad, k = i - r * Kpad;
    float v = (k < K) ? in[(size_t)r * K + k] : 0.0f;
    bf16 h, l; split_val(v, h, l);
    hi[i] = h; lo[i] = l;
}

// ---------------- state init ----------------
__global__ void init_states_kernel(const float* __restrict__ L_init,
                                   const float* __restrict__ C_init) {
    int i = blockIdx.x * blockDim.x + threadIdx.x;
    const int totL = NLITS * E;
    if (i < totL) {
        bf16 h, l; split_val(L_init[i & (E - 1)], h, l);
        g_LhH[i] = h; g_LhL[i] = l; g_Lc[i] = 0.0f;
    } else if (i < totL + NCLS * E) {
        int j = i - totL;
        bf16 h, l; split_val(C_init[j & (E - 1)], h, l);
        g_ChH[j] = h; g_ChL[j] = l; g_Cc[j] = 0.0f;
    }
}

// ---------------- bf16x3 tensor-core GEMM ----------------
// C = act( sum_seg A[seg] @ B[seg]^T + bias ); A:[M,Kpad] bf16 row-major,
// B:[N,Kpad] bf16 row-major. Output: fp32 [M,opitch] or split hi/lo bf16.
// blockIdx.z picks one of two independent problems.
struct GP {
    const bf16* A[6];
    const bf16* B[6];
    const float* bias;
    float* outf;                 // used when !SPLIT_OUT
    bf16* oh; bf16* ol;          // used when SPLIT_OUT
    int M;
    int nseg;
};

#define BK 32
#define SPITCH 40   // bf16 elements per smem row (32 + 8 pad) -> 80B stride

__device__ __forceinline__ unsigned smem_u32(const void* p) {
    return (unsigned)__cvta_generic_to_shared(p);
}

template <bool RELU, bool SPLIT_OUT>
__global__ void __launch_bounds__(256) gemm_bf16x3_kernel(GP p0, GP p1, int N, int Kpad, int opitch)
{
    const GP p = (blockIdx.z == 0) ? p0 : p1;
    const int m0 = blockIdx.y * 128;
    if (m0 >= p.M) return;
    const int n0 = blockIdx.x * 128;

    __shared__ bf16 As[2][128][SPITCH];
    __shared__ bf16 Bs[2][128][SPITCH];

    const int tid = threadIdx.x;
    const int lane = tid & 31;
    const int wid = tid >> 5;
    const int wm0 = (wid & 3) * 32;     // warp m offset (4 warps over M)
    const int wn0 = (wid >> 2) * 64;    // warp n offset (2 warps over N)

    const int ntiles = Kpad / BK;
    const int total = ntiles * p.nseg;

    float c[2][8][4];
#pragma unroll
    for (int a = 0; a < 2; a++)
#pragma unroll
        for (int b = 0; b < 8; b++)
#pragma unroll
            for (int d = 0; d < 4; d++) c[a][b][d] = 0.0f;

    uint4 va[2], vb[2];

    // gmem -> regs for tile ti
    auto load_g = [&](int ti) {
        int seg = ti / ntiles;
        int k0 = (ti - seg * ntiles) * BK;
        const bf16* Ap = p.A[seg];
        const bf16* Bp = p.B[seg];
#pragma unroll
        for (int i = 0; i < 2; i++) {
            int idx = tid + i * 256;          // 0..511
            int row = idx >> 2;               // 0..127
            int q = idx & 3;                  // 16B chunk
            uint4 v = make_uint4(0, 0, 0, 0);
            int gr = m0 + row;
            if (gr < p.M) v = *(const uint4*)(Ap + (size_t)gr * Kpad + k0 + q * 8);
            va[i] = v;
            uint4 w = make_uint4(0, 0, 0, 0);
            int gn = n0 + row;
            if (gn < N) w = *(const uint4*)(Bp + (size_t)gn * Kpad + k0 + q * 8);
            vb[i] = w;
        }
    };
    // regs -> smem buffer
    auto store_s = [&](int buf) {
#pragma unroll
        for (int i = 0; i < 2; i++) {
            int idx = tid + i * 256;
            int row = idx >> 2;
            int q = idx & 3;
            *(uint4*)&As[buf][row][q * 8] = va[i];
            *(uint4*)&Bs[buf][row][q * 8] = vb[i];
        }
    };

    load_g(0);
    store_s(0);
    __syncthreads();

    int buf = 0;
    for (int t = 0; t < total; t++) {
        if (t + 1 < total) load_g(t + 1);

        // compute on buf
#pragma unroll
        for (int kk = 0; kk < 2; kk++) {
            uint32_t afrag[2][4];
#pragma unroll
            for (int mt = 0; mt < 2; mt++) {
                unsigned addr = smem_u32(&As[buf][wm0 + mt * 16 + (lane & 15)]
                                            [kk * 16 + ((lane >> 4) * 8)]);
                asm volatile("ldmatrix.sync.aligned.m8n8.x4.shared.b16 {%0,%1,%2,%3}, [%4];"
                             : "=r"(afrag[mt][0]), "=r"(afrag[mt][1]),
                               "=r"(afrag[mt][2]), "=r"(afrag[mt][3])
                             : "r"(addr));
            }
            uint32_t bfrag[4][4];
#pragma unroll
            for (int ng = 0; ng < 4; ng++) {
                int brow = wn0 + ng * 16 + (lane & 7) + (((lane >> 4) & 1) << 3);
                int bcol = kk * 16 + (((lane >> 3) & 1) * 8);
                unsigned addr = smem_u32(&Bs[buf][brow][bcol]);
                asm volatile("ldmatrix.sync.aligned.m8n8.x4.shared.b16 {%0,%1,%2,%3}, [%4];"
                             : "=r"(bfrag[ng][0]), "=r"(bfrag[ng][1]),
                               "=r"(bfrag[ng][2]), "=r"(bfrag[ng][3])
                             : "r"(addr));
            }
#pragma unroll
            for (int mt = 0; mt < 2; mt++) {
#pragma unroll
                for (int ng = 0; ng < 4; ng++) {
                    asm volatile(
                        "mma.sync.aligned.m16n8k16.row.col.f32.bf16.bf16.f32 "
                        "{%0,%1,%2,%3}, {%4,%5,%6,%7}, {%8,%9}, {%0,%1,%2,%3};"
                        : "+f"(c[mt][2 * ng][0]), "+f"(c[mt][2 * ng][1]),
                          "+f"(c[mt][2 * ng][2]), "+f"(c[mt][2 * ng][3])
                        : "r"(afrag[mt][0]), "r"(afrag[mt][1]),
                          "r"(afrag[mt][2]), "r"(afrag[mt][3]),
                          "r"(bfrag[ng][0]), "r"(bfrag[ng][1]));
                    asm volatile(
                        "mma.sync.aligned.m16n8k16.row.col.f32.bf16.bf16.f32 "
                        "{%0,%1,%2,%3}, {%4,%5,%6,%7}, {%8,%9}, {%0,%1,%2,%3};"
                        : "+f"(c[mt][2 * ng + 1][0]), "+f"(c[mt][2 * ng + 1][1]),
                          "+f"(c[mt][2 * ng + 1][2]), "+f"(c[mt][2 * ng + 1][3])
                        : "r"(afrag[mt][0]), "r"(afrag[mt][1]),
                          "r"(afrag[mt][2]), "r"(afrag[mt][3]),
                          "r"(bfrag[ng][2]), "r"(bfrag[ng][3]));
                }
            }
        }

        if (t + 1 < total) store_s(buf ^ 1);
        __syncthreads();
        buf ^= 1;
    }

    // ---------------- epilogue ----------------
    const int g = lane >> 2;
    const int tg = lane & 3;
#pragma unroll
    for (int mt = 0; mt < 2; mt++) {
#pragma unroll
        for (int j = 0; j < 8; j++) {
            int col = n0 + wn0 + j * 8 + tg * 2;
            if (col >= N) continue;
#pragma unroll
            for (int half = 0; half < 2; half++) {
                int row = m0 + wm0 + mt * 16 + g + half * 8;
                if (row >= p.M) continue;
                float v0 = c[mt][j][half * 2 + 0] + p.bias[col];
                float v1 = c[mt][j][half * 2 + 1] + p.bias[col + 1];
                if (RELU) { v0 = fmaxf(v0, 0.0f); v1 = fmaxf(v1, 0.0f); }
                size_t off = (size_t)row * opitch + col;
                if (SPLIT_OUT) {
                    bf16 h0, l0, h1, l1;
                    split_val(v0, h0, l0);
                    split_val(v1, h1, l1);
                    *(bf162*)(p.oh + off) = __halves2bfloat162(h0, h1);
                    *(bf162*)(p.ol + off) = __halves2bfloat162(l0, l1);
                } else {
                    *(float2*)(p.outf + off) = make_float2(v0, v1);
                }
            }
        }
    }
}

template <bool RELU, bool SPLIT_OUT>
static inline void launch_gemm(GP p0, GP p1, int nz, int N, int Kpad, int opitch) {
    int mmax = p0.M;
    if (nz > 1 && p1.M > mmax) mmax = p1.M;
    dim3 grid((N + 127) / 128, (mmax + 127) / 128, nz);
    gemm_bf16x3_kernel<RELU, SPLIT_OUT><<<grid, 256>>>(p0, p1, N, Kpad, opitch);
}

// ---------------- SpMM gather (hi/lo in, hi/lo out), E=128 ----------------
__global__ void spmm_gather_kernel(const int* __restrict__ idx, const int* __restrict__ len,
                                   int stride,
                                   const bf16* __restrict__ inH, const bf16* __restrict__ inL,
                                   bf16* __restrict__ outH, bf16* __restrict__ outL,
                                   int nrows) {
    int r = (blockIdx.x * blockDim.x + threadIdx.x) >> 5;
    if (r >= nrows) return;
    int lane = threadIdx.x & 31;
    const int* lst = idx + (size_t)r * stride;
    int n = len[r];
    float acc0 = 0.f, acc1 = 0.f, acc2 = 0.f, acc3 = 0.f;
    for (int j = 0; j < n; j++) {
        size_t base = (size_t)lst[j] * E + lane * 4;
        bf162 h01 = *(const bf162*)(inH + base);
        bf162 h23 = *(const bf162*)(inH + base + 2);
        bf162 l01 = *(const bf162*)(inL + base);
        bf162 l23 = *(const bf162*)(inL + base + 2);
        float2 fh01 = __bfloat1622float2(h01), fh23 = __bfloat1622float2(h23);
        float2 fl01 = __bfloat1622float2(l01), fl23 = __bfloat1622float2(l23);
        acc0 += fh01.x + fl01.x; acc1 += fh01.y + fl01.y;
        acc2 += fh23.x + fl23.x; acc3 += fh23.y + fl23.y;
    }
    size_t ob = (size_t)r * E + lane * 4;
    bf16 h, l;
    split_val(acc0, h, l); outH[ob + 0] = h; outL[ob + 0] = l;
    split_val(acc1, h, l); outH[ob + 1] = h; outL[ob + 1] = l;
    split_val(acc2, h, l); outH[ob + 2] = h; outL[ob + 2] = l;
    split_val(acc3, h, l); outH[ob + 3] = h; outL[ob + 3] = l;
}

// ---------------- LSTM pointwise (both node types) ----------------
__device__ __forceinline__ float sigmoidf_(float x) { return 1.0f / (1.0f + expf(-x)); }

__global__ void lstm_pointwise_both(const float* __restrict__ gC,
                                    const float* __restrict__ gL) {
    int i = blockIdx.x * blockDim.x + threadIdx.x;
    const int totalC = NCLS * E;
    if (i >= totalC + NLITS * E) return;

    const float* gmat; float* cvec; bf16 *hH, *hL; int e;
    if (i < totalC) { gmat = gC; cvec = g_Cc; hH = g_ChH; hL = g_ChL; e = i; }
    else            { gmat = gL; cvec = g_Lc; hH = g_LhH; hL = g_LhL; e = i - totalC; }

    int row = e >> 7;
    int col = e & (E - 1);
    const float* gr = gmat + (size_t)row * NG;
    float ig = sigmoidf_(gr[col]);
    float fg = sigmoidf_(gr[E + col]);
    float gg = tanhf(gr[2 * E + col]);
    float og = sigmoidf_(gr[3 * E + col]);
    float c2 = fg * cvec[e] + ig * gg;
    cvec[e] = c2;
    float hv = og * tanhf(c2);
    bf16 h, l; split_val(hv, h, l);
    hH[e] = h; hL[e] = l;
}

// ---------------- vote + reduction ----------------
__global__ void vote_partial_kernel(const bf16* __restrict__ X2H, const bf16* __restrict__ X2L,
                                    const float* __restrict__ W3,
                                    const float* __restrict__ b3,
                                    float* __restrict__ partials) {
    int warp = (blockIdx.x * blockDim.x + threadIdx.x) >> 5;
    int lane = threadIdx.x & 31;
    float vote = 0.0f;
    if (warp < NLITS) {
        const bf16* xh = X2H + (size_t)warp * K3P;
        const bf16* xl = X2L + (size_t)warp * K3P;
        float s = 0.0f;
        for (int jj = lane; jj < H2; jj += 32)
            s += (__bfloat162float(xh[jj]) + __bfloat162float(xl[jj])) * W3[jj];
#pragma unroll
        for (int o = 16; o; o >>= 1) s += __shfl_down_sync(0xffffffffu, s, o);
        if (lane == 0) vote = sigmoidf_(s + b3[0]);
    }
    __shared__ float sm[8];
    if (lane == 0) sm[threadIdx.x >> 5] = vote;
    __syncthreads();
    if (threadIdx.x == 0) {
        float t = 0.0f;
        for (int w = 0; w < 8; w++) t += sm[w];
        partials[blockIdx.x] = t;
    }
}

__global__ void finalize_kernel(const float* __restrict__ partials, int n,
                                float* __restrict__ out) {
    __shared__ float sm[512];
    float s = 0.0f;
    for (int i = threadIdx.x; i < n; i += blockDim.x) s += partials[i];
    sm[threadIdx.x] = s;
    __syncthreads();
    for (int o = 256; o; o >>= 1) {
        if (threadIdx.x < o) sm[threadIdx.x] += sm[threadIdx.x + o];
        __syncthreads();
    }
    if (threadIdx.x == 0) {
        float avg = sm[0] / (float)NLITS;
        out[0] = logf(avg / (1.0f - avg));
    }
}

// ---------------- host ----------------
static inline void split_w(const float* in, bf16* hi, bf16* lo, int rows, int K, int Kpad) {
    int n = rows * Kpad;
    split_weight_kernel<<<(n + 255) / 256, 256>>>(in, hi, lo, rows, K, Kpad);
}

#define SYM(var, sym) cudaGetSymbolAddress((void**)&var, sym)

extern "C" void kernel_launch(void* const* d_in, const int* in_sizes, int n_in,
                              void* d_out, int out_size) {
    const float* M      = (const float*)d_in[0];
    const float* L_init = (const float*)d_in[1];
    const float* C_init = (const float*)d_in[2];
    const float* LC_W1 = (const float*)d_in[3];  const float* LC_b1 = (const float*)d_in[4];
    const float* LC_W2 = (const float*)d_in[5];  const float* LC_b2 = (const float*)d_in[6];
    const float* LC_W3 = (const float*)d_in[7];  const float* LC_b3 = (const float*)d_in[8];
    const float* CL_W1 = (const float*)d_in[9];  const float* CL_b1 = (const float*)d_in[10];
    const float* CL_W2 = (const float*)d_in[11]; const float* CL_b2 = (const float*)d_in[12];
    const float* CL_W3 = (const float*)d_in[13]; const float* CL_b3 = (const float*)d_in[14];
    const float* L_Wih = (const float*)d_in[15]; const float* L_Whh = (const float*)d_in[16];
    const float* L_b   = (const float*)d_in[17];
    const float* C_Wih = (const float*)d_in[18]; const float* C_Whh = (const float*)d_in[19];
    const float* C_b   = (const float*)d_in[20];
    const float* V_W1 = (const float*)d_in[21];  const float* V_b1 = (const float*)d_in[22];
    const float* V_W2 = (const float*)d_in[23];  const float* V_b2 = (const float*)d_in[24];
    const float* V_W3 = (const float*)d_in[25];  const float* V_b3 = (const float*)d_in[26];
    float* out = (float*)d_out;

    bf16 *LhH,*LhL,*ChH,*ChL, *b1LH,*b1LL,*b1CH,*b1CL, *b2LH,*b2LL,*b2CH,*b2CL;
    bf16 *mlpLH,*mlpLL,*mlpCH,*mlpCL, *msgLH,*msgLL,*msgCH,*msgCL;
    bf16 *LC1H,*LC1L,*LC2H,*LC2L,*LC3H,*LC3L, *CL1H,*CL1L,*CL2H,*CL2L,*CL3H,*CL3L;
    bf16 *CWiH,*CWiL,*CWhH,*CWhL,*LWiH,*LWiL,*LWhH,*LWhL, *VW1H,*VW1L,*VW2H,*VW2L;
    float *gatesC,*gatesL,*partials;
    int *lit_idx,*lit_len,*cls_idx,*cls_len;

    SYM(LhH, g_LhH); SYM(LhL, g_LhL); SYM(ChH, g_ChH); SYM(ChL, g_ChL);
    SYM(b1LH, g_b1LH); SYM(b1LL, g_b1LL); SYM(b1CH, g_b1CH); SYM(b1CL, g_b1CL);
    SYM(b2LH, g_b2LH); SYM(b2LL, g_b2LL); SYM(b2CH, g_b2CH); SYM(b2CL, g_b2CL);
    SYM(mlpLH, g_mlpLH); SYM(mlpLL, g_mlpLL); SYM(mlpCH, g_mlpCH); SYM(mlpCL, g_mlpCL);
    SYM(msgLH, g_msgLH); SYM(msgLL, g_msgLL); SYM(msgCH, g_msgCH); SYM(msgCL, g_msgCL);
    SYM(LC1H, g_LC1H); SYM(LC1L, g_LC1L); SYM(LC2H, g_LC2H); SYM(LC2L, g_LC2L);
    SYM(LC3H, g_LC3H); SYM(LC3L, g_LC3L);
    SYM(CL1H, g_CL1H); SYM(CL1L, g_CL1L); SYM(CL2H, g_CL2H); SYM(CL2L, g_CL2L);
    SYM(CL3H, g_CL3H); SYM(CL3L, g_CL3L);
    SYM(CWiH, g_CWiH); SYM(CWiL, g_CWiL); SYM(CWhH, g_CWhH); SYM(CWhL, g_CWhL);
    SYM(LWiH, g_LWiH); SYM(LWiL, g_LWiL); SYM(LWhH, g_LWhH); SYM(LWhL, g_LWhL);
    SYM(VW1H, g_VW1H); SYM(VW1L, g_VW1L); SYM(VW2H, g_VW2H); SYM(VW2L, g_VW2L);
    SYM(gatesC, g_gatesC); SYM(gatesL, g_gatesL); SYM(partials, g_partials);
    SYM(lit_idx, g_lit_idx); SYM(lit_len, g_lit_len);
    SYM(cls_idx, g_cls_idx); SYM(cls_len, g_cls_len);

    // adjacency
    build_lit_kernel<<<(NLITS + 7) / 8, 256>>>(M);
    build_cls_kernel<<<(NCLS + 7) / 8, 256>>>(M);

    // weight splits (once per replay; cheap)
    split_w(LC_W1, LC1H, LC1L, H1, E,  K1P);
    split_w(LC_W2, LC2H, LC2L, H2, H1, K2P);
    split_w(LC_W3, LC3H, LC3L, E,  H2, K3P);
    split_w(CL_W1, CL1H, CL1L, H1, E,  K1P);
    split_w(CL_W2, CL2H, CL2L, H2, H1, K2P);
    split_w(CL_W3, CL3H, CL3L, E,  H2, K3P);
    split_w(C_Wih, CWiH, CWiL, NG, E,  K1P);
    split_w(C_Whh, CWhH, CWhL, NG, E,  K1P);
    split_w(L_Wih, LWiH, LWiL, NG, E,  K1P);
    split_w(L_Whh, LWhH, LWhL, NG, E,  K1P);
    split_w(V_W1,  VW1H, VW1L, H1, E,  K1P);
    split_w(V_W2,  VW2H, VW2L, H2, H1, K2P);

    // state init
    init_states_kernel<<<((NLITS + NCLS) * E + 255) / 256, 256>>>(L_init, C_init);

    GP dummy = {};

    for (int t = 0; t < TSTEPS; t++) {
        // MLP layer 1 (lit uses LC weights, cls uses CL weights)
        GP a1 = {{LhH, LhH, LhL}, {LC1H, LC1L, LC1H}, LC_b1, nullptr, b1LH, b1LL, NLITS, 3};
        GP b1 = {{ChH, ChH, ChL}, {CL1H, CL1L, CL1H}, CL_b1, nullptr, b1CH, b1CL, NCLS, 3};
        launch_gemm<true, true>(a1, b1, 2, H1, K1P, K2P);

        // MLP layer 2
        GP a2 = {{b1LH, b1LH, b1LL}, {LC2H, LC2L, LC2H}, LC_b2, nullptr, b2LH, b2LL, NLITS, 3};
        GP b2 = {{b1CH, b1CH, b1CL}, {CL2H, CL2L, CL2H}, CL_b2, nullptr, b2CH, b2CL, NCLS, 3};
        launch_gemm<true, true>(a2, b2, 2, H2, K2P, K3P);

        // MLP layer 3 (no relu)
        GP a3 = {{b2LH, b2LH, b2LL}, {LC3H, LC3L, LC3H}, LC_b3, nullptr, mlpLH, mlpLL, NLITS, 3};
        GP b3 = {{b2CH, b2CH, b2CL}, {CL3H, CL3L, CL3H}, CL_b3, nullptr, mlpCH, mlpCL, NCLS, 3};
        launch_gemm<false, true>(a3, b3, 2, E, K3P, E);

        // sparse aggregation
        spmm_gather_kernel<<<(NCLS + 7) / 8, 256>>>(cls_idx, cls_len, CLS_STRIDE,
                                                    mlpLH, mlpLL, msgCH, msgCL, NCLS);
        spmm_gather_kernel<<<(NLITS + 7) / 8, 256>>>(lit_idx, lit_len, LIT_STRIDE,
                                                     mlpCH, mlpCL, msgLH, msgLL, NLITS);

        // LSTM gates: msgs@Wih^T + h@Whh^T + b  (pre-update h), fp32 out
        GP ga = {{msgCH, msgCH, msgCL, ChH, ChH, ChL},
                 {CWiH, CWiL, CWiH, CWhH, CWhL, CWhH}, C_b, gatesC, nullptr, nullptr, NCLS, 6};
        GP gb = {{msgLH, msgLH, msgLL, LhH, LhH, LhL},
                 {LWiH, LWiL, LWiH, LWhH, LWhL, LWhH}, L_b, gatesL, nullptr, nullptr, NLITS, 6};
        launch_gemm<false, false>(ga, gb, 2, NG, K1P, NG);

        // pointwise state update
        lstm_pointwise_both<<<((NCLS + NLITS) * E + 255) / 256, 256>>>(gatesC, gatesL);
    }

    // final vote MLP + mean + logit
    GP v1 = {{LhH, LhH, LhL}, {VW1H, VW1L, VW1H}, V_b1, nullptr, b1LH, b1LL, NLITS, 3};
    launch_gemm<true, true>(v1, dummy, 1, H1, K1P, K2P);
    GP v2 = {{b1LH, b1LH, b1LL}, {VW2H, VW2L, VW2H}, V_b2, nullptr, b2LH, b2LL, NLITS, 3};
    launch_gemm<true, true>(v2, dummy, 1, H2, K2P, K3P);
    vote_partial_kernel<<<VOTE_BLOCKS, 256>>>(b2LH, b2LL, V_W3, V_b3, partials);
    finalize_kernel<<<1, 512>>>(partials, VOTE_BLOCKS, out);
}